// round 5
// baseline (speedup 1.0000x reference)
#include <cuda_runtime.h>

// ---------------------------------------------------------------------------
// Fused involution block for GB300 (sm_103a), fp32 with packed f32x2 FMA.
// R2/R3: LDS.128 both operands + 2x2 register blocking in both GEMMs to
// relieve the shared-memory/LSU bottleneck seen in R1 ncu (L1=75%, fma=20%).
// (R2 bench was an infra failure; this is the same theory, micro-cleaned.)
// ---------------------------------------------------------------------------

#define U64 unsigned long long

__device__ __forceinline__ U64 ffma2(U64 a, U64 b, U64 c) {
    U64 d;
    asm("fma.rn.f32x2 %0, %1, %2, %3;" : "=l"(d) : "l"(a), "l"(b), "l"(c));
    return d;
}
__device__ __forceinline__ U64 pack2(float lo, float hi) {
    U64 d;
    asm("mov.b64 %0, {%1, %2};" : "=l"(d) : "f"(lo), "f"(hi));
    return d;
}
__device__ __forceinline__ float2 unpack2(U64 v) {
    float2 r;
    asm("mov.b64 {%0, %1}, %2;" : "=f"(r.x), "=f"(r.y) : "l"(v));
    return r;
}

namespace cfg {
constexpr int C   = 256;
constexpr int HW  = 56;
constexpr int G   = 16;
constexpr int Cg  = 16;
constexpr int KS  = 7;
constexpr int PAD = 3;
constexpr int CR  = 64;          // bottleneck channels
constexpr int TH  = 4;           // tile height
constexpr int TW  = 8;           // tile width
constexpr int TP  = TH * TW;     // 32 pixels / tile
constexpr int HALO_H = TH + 2 * PAD;   // 10
constexpr int HALO_W = TW + 2 * PAD;   // 14
constexpr float EPSV = 1e-5f;

// shared memory layout (float offsets)
constexpr int OFF_TS  = 0;                   // ts[64][32]   2048 floats
constexpr int OFF_A   = 2048;                // overlapped region
// phase 1 view: W1d float4[64][33] (padded rows) then xs[64][32]
constexpr int W1D_ROW = 33;                  // float4 per cc row (pad vs 32)
constexpr int OFF_XS  = OFF_A + 64 * W1D_ROW * 4;   // 2048 + 8448
// phase 2/3 view: W2d float4[64][25], wg[49][32], xh[16][10][14]
constexpr int W2D_ROW = 25;
constexpr int OFF_WG  = OFF_A + 64 * W2D_ROW * 4;   // 2048 + 6400
constexpr int OFF_XH  = OFF_WG + 49 * TP;           // + 1568
constexpr int SMEM_FLOATS = OFF_XS + 2048;          // 12544 floats = 49 KiB
}

using namespace cfg;

__global__ void __launch_bounds__(256) involution_fused_kernel(
    const float* __restrict__ x,
    const float* __restrict__ W1, const float* __restrict__ b1,
    const float* __restrict__ gamma, const float* __restrict__ beta,
    const float* __restrict__ mean, const float* __restrict__ var,
    const float* __restrict__ W2, const float* __restrict__ b2,
    float* __restrict__ out)
{
    extern __shared__ float smem[];
    float* ts = smem + OFF_TS;
    float* xs = smem + OFF_XS;
    float* wg = smem + OFF_WG;
    float* xh = smem + OFF_XH;
    ulonglong2* W1d = (ulonglong2*)(smem + OFF_A);   // [cc][33] each = (w_o0 dup | w_o1 dup)
    ulonglong2* W2d = (ulonglong2*)(smem + OFF_A);   // [cc][25] each = (w_k0 dup | w_k1 dup)

    const int tid = threadIdx.x;
    const int b   = blockIdx.z;
    const int h0  = blockIdx.y * TH;
    const int w0  = blockIdx.x * TW;

    // ================= Phase 1: t = relu(BN(x @ W1^T + b1)) ================
    // thread: op = tid>>3 owns outs (2op, 2op+1); pxq = tid&7 owns px 4pxq..+3
    const int op  = tid >> 3;
    const int pxq = tid & 7;
    U64 a00 = 0, a01 = 0, a10 = 0, a11 = 0;   // (o0:p01,p23) (o1:p01,p23)

    for (int chunk = 0; chunk < 4; chunk++) {
        const int c0 = chunk * 64;
        // x chunk [64ch][32px] -> xs (float4 coalesced)
        {
            int idx = tid;
            #pragma unroll
            for (int r = 0; r < 2; r++) {
                const int cc = idx >> 3, py = (idx >> 1) & 3, hf = idx & 1;
                const float4 v = *(const float4*)&x[((b * C + c0 + cc) * HW + h0 + py) * HW + w0 + hf * 4];
                *(float4*)&xs[cc * TP + py * TW + hf * 4] = v;
                idx += 256;
            }
        }
        // W1 chunk -> W1d[cc][o2] = (W1[2o2][c0+cc] x2, W1[2o2+1][c0+cc] x2)
        #pragma unroll
        for (int r = 0; r < 8; r++) {
            const int idx = tid + 256 * r;     // 0..2047
            const int cc = idx & 63, o2 = idx >> 6;   // o2: 0..31
            const float v0 = __ldg(&W1[(2 * o2) * C + c0 + cc]);
            const float v1 = __ldg(&W1[(2 * o2 + 1) * C + c0 + cc]);
            *(float4*)&W1d[cc * W1D_ROW + o2] = make_float4(v0, v0, v1, v1);
        }
        __syncthreads();

        #pragma unroll 8
        for (int cc = 0; cc < 64; cc++) {
            const ulonglong2 tv = *(const ulonglong2*)&xs[cc * TP + pxq * 4];
            const ulonglong2 wv = W1d[cc * W1D_ROW + op];
            a00 = ffma2(wv.x, tv.x, a00);
            a01 = ffma2(wv.x, tv.y, a01);
            a10 = ffma2(wv.y, tv.x, a10);
            a11 = ffma2(wv.y, tv.y, a11);
        }
        __syncthreads();
    }

    // BN fold + relu + store t (ts[o][32px])
    #pragma unroll
    for (int u = 0; u < 2; u++) {
        const int o = 2 * op + u;
        const float a  = __ldg(&gamma[o]) * rsqrtf(__ldg(&var[o]) + EPSV);
        const float bb = __ldg(&b1[o]) * a + __ldg(&beta[o]) - __ldg(&mean[o]) * a;
        const float2 p0 = unpack2(u ? a10 : a00);
        const float2 p1 = unpack2(u ? a11 : a01);
        float4 r;
        r.x = fmaxf(p0.x * a + bb, 0.f);
        r.y = fmaxf(p0.y * a + bb, 0.f);
        r.z = fmaxf(p1.x * a + bb, 0.f);
        r.w = fmaxf(p1.y * a + bb, 0.f);
        *(float4*)&ts[o * TP + pxq * 4] = r;
    }
    __syncthreads();

    // ================= Phase 2+3 per group ==================================
    const int kp   = tid >> 3;        // k-pair 0..24 active (k = 2kp, 2kp+1)
    const int pxq2 = tid & 7;
    const int pxp  = tid & 15;        // phase-3: pixel pair p = 2*pxp
    const int c3   = tid >> 4;        // phase-3: channel within group
    const int py3  = pxp >> 2;
    const int col3 = (pxp & 3) * 2;
    const float* xh3 = &xh[c3 * (HALO_H * HALO_W) + py3 * HALO_W + col3];
    float* out3 = &out[((b * C + c3) * HW + h0 + py3) * HW + w0 + col3];

    for (int g = 0; g < G; g++) {
        // W2 group -> W2d[cc][kq] = (w_k0 x2, w_k1 x2)
        {
            int idx = tid;
            #pragma unroll
            for (int r = 0; r < 7; r++) {       // 7*256 = 1792 >= 1600
                if (idx < 1600) {
                    const int cc = idx & 63, kq = idx >> 6;   // kq 0..24
                    const int k0 = 2 * kq, k1 = 2 * kq + 1;
                    const float v0 = __ldg(&W2[(g * 49 + k0) * CR + cc]);
                    const float v1 = (k1 < 49) ? __ldg(&W2[(g * 49 + k1) * CR + cc]) : 0.f;
                    *(float4*)&W2d[cc * W2D_ROW + kq] = make_float4(v0, v0, v1, v1);
                }
                idx += 256;
            }
        }
        // input halo for this group's 16 channels (zero padded)
        for (int idx = tid; idx < Cg * HALO_H * HALO_W; idx += 256) {
            const int c   = idx / (HALO_H * HALO_W);
            const int rem = idx - c * (HALO_H * HALO_W);
            const int r   = rem / HALO_W;
            const int cl  = rem - r * HALO_W;
            const int gh = h0 + r - PAD, gw = w0 + cl - PAD;
            float v = 0.f;
            if ((unsigned)gh < (unsigned)HW && (unsigned)gw < (unsigned)HW)
                v = __ldg(&x[((b * C + g * Cg + c) * HW + gh) * HW + gw]);
            xh[idx] = v;
        }
        __syncthreads();

        // phase 2: wg[k][p] = sum_cc W2g[k][cc] * t[cc][p] + b2[k]
        if (kp < 25) {
            const int k0 = 2 * kp, k1 = 2 * kp + 1;
            const float z0 = __ldg(&b2[g * 49 + k0]);
            const float z1 = (k1 < 49) ? __ldg(&b2[g * 49 + k1]) : 0.f;
            U64 b00 = pack2(z0, z0), b01 = b00;
            U64 b10 = pack2(z1, z1), b11 = b10;
            #pragma unroll 8
            for (int cc = 0; cc < 64; cc++) {
                const ulonglong2 tv = *(const ulonglong2*)&ts[cc * TP + pxq2 * 4];
                const ulonglong2 wv = W2d[cc * W2D_ROW + kp];
                b00 = ffma2(wv.x, tv.x, b00);
                b01 = ffma2(wv.x, tv.y, b01);
                b10 = ffma2(wv.y, tv.x, b10);
                b11 = ffma2(wv.y, tv.y, b11);
            }
            *(U64*)&wg[k0 * TP + pxq2 * 4]     = b00;
            *(U64*)&wg[k0 * TP + pxq2 * 4 + 2] = b01;
            if (k1 < 49) {
                *(U64*)&wg[k1 * TP + pxq2 * 4]     = b10;
                *(U64*)&wg[k1 * TP + pxq2 * 4 + 2] = b11;
            }
        }
        __syncthreads();

        // phase 3: involution — thread owns (channel c3, pixel pair 2*pxp)
        {
            float o0 = 0.f, o1 = 0.f;
            #pragma unroll
            for (int i = 0; i < KS; i++) {
                const float* xrow = xh3 + i * HALO_W;
                float xr[9];
                const float2 xa = *(const float2*)(xrow + 0);
                const float2 xb = *(const float2*)(xrow + 2);
                const float2 xc = *(const float2*)(xrow + 4);
                const float2 xd = *(const float2*)(xrow + 6);
                xr[0] = xa.x; xr[1] = xa.y; xr[2] = xb.x; xr[3] = xb.y;
                xr[4] = xc.x; xr[5] = xc.y; xr[6] = xd.x; xr[7] = xd.y;
                xr[8] = xrow[8];
                #pragma unroll
                for (int j = 0; j < KS; j++) {
                    const float2 wv = *(const float2*)&wg[(i * KS + j) * TP + 2 * pxp];
                    o0 = fmaf(xr[j],     wv.x, o0);
                    o1 = fmaf(xr[j + 1], wv.y, o1);
                }
            }
            *(float2*)(out3 + g * Cg * HW * HW) = make_float2(o0, o1);
        }
        __syncthreads();
    }
}

extern "C" void kernel_launch(void* const* d_in, const int* in_sizes, int n_in,
                              void* d_out, int out_size) {
    const float* x     = (const float*)d_in[0];
    const float* W1    = (const float*)d_in[1];
    const float* b1    = (const float*)d_in[2];
    const float* gamma = (const float*)d_in[3];
    const float* beta  = (const float*)d_in[4];
    const float* mean  = (const float*)d_in[5];
    const float* var   = (const float*)d_in[6];
    const float* W2    = (const float*)d_in[7];
    const float* b2    = (const float*)d_in[8];
    float* out = (float*)d_out;

    const size_t smem_bytes = (size_t)SMEM_FLOATS * sizeof(float);  // 49 KiB
    cudaFuncSetAttribute(involution_fused_kernel,
                         cudaFuncAttributeMaxDynamicSharedMemorySize, (int)smem_bytes);

    dim3 grid(HW / TW, HW / TH, 4);   // 7 x 14 x 4 = 392 blocks
    involution_fused_kernel<<<grid, 256, smem_bytes>>>(
        x, W1, b1, gamma, beta, mean, var, W2, b2, out);
}

// round 6
// speedup vs baseline: 1.1339x; 1.1339x over previous
#include <cuda_runtime.h>
#include <cstdint>

// ---------------------------------------------------------------------------
// R5: two-kernel fused involution for GB300 (sm_103a).
//  Kernel A: t = relu(BN(x @ W1^T + b1))  -> __device__ scratch (3.2 MB)
//  Kernel B: per-pixel kernel GEMM (f32x2) + involution, group-split x4 for
//            occupancy; halo via cp.async zfill; phase-3 (2ch x 2px)/thread.
// ---------------------------------------------------------------------------

#define U64 unsigned long long

__device__ __forceinline__ U64 ffma2(U64 a, U64 b, U64 c) {
    U64 d;
    asm("fma.rn.f32x2 %0, %1, %2, %3;" : "=l"(d) : "l"(a), "l"(b), "l"(c));
    return d;
}
__device__ __forceinline__ U64 pack2(float lo, float hi) {
    U64 d;
    asm("mov.b64 %0, {%1, %2};" : "=l"(d) : "f"(lo), "f"(hi));
    return d;
}
__device__ __forceinline__ float2 unpack2(U64 v) {
    float2 r;
    asm("mov.b64 {%0, %1}, %2;" : "=f"(r.x), "=f"(r.y) : "l"(v));
    return r;
}
__device__ __forceinline__ void cp_async16(void* s, const void* g) {
    uint32_t sa = (uint32_t)__cvta_generic_to_shared(s);
    asm volatile("cp.async.cg.shared.global [%0], [%1], 16;" :: "r"(sa), "l"(g));
}
__device__ __forceinline__ void cp_async4z(void* s, const void* g, int srcsz) {
    uint32_t sa = (uint32_t)__cvta_generic_to_shared(s);
    asm volatile("cp.async.ca.shared.global [%0], [%1], 4, %2;" :: "r"(sa), "l"(g), "r"(srcsz));
}
__device__ __forceinline__ void cp_commit()  { asm volatile("cp.async.commit_group;"); }
__device__ __forceinline__ void cp_wait1()   { asm volatile("cp.async.wait_group 1;"); }
__device__ __forceinline__ void cp_wait0()   { asm volatile("cp.async.wait_group 0;"); }

namespace cfg {
constexpr int C   = 256;
constexpr int HW  = 56;
constexpr int G   = 16;
constexpr int Cg  = 16;
constexpr int KS  = 7;
constexpr int PAD = 3;
constexpr int CR  = 64;
constexpr int TH  = 4;
constexpr int TW  = 8;
constexpr int TP  = TH * TW;             // 32 pixels / tile
constexpr int HALO_H = TH + 2 * PAD;     // 10
constexpr int HALO_W = TW + 2 * PAD;     // 14
constexpr int HALO_CH = HALO_H * HALO_W; // 140
constexpr int HALO_SZ = Cg * HALO_CH;    // 2240
constexpr float EPSV = 1e-5f;
constexpr int SPLIT = 4;                 // groups split across blocks

// Kernel A smem
constexpr int W1D_ROW = 33;                         // float4 per cc row (padded)
constexpr int A_OFF_XS = 64 * W1D_ROW * 4;          // 8448
constexpr int A_SMEM_FLOATS = A_OFF_XS + 2048;      // 10496 = 41 KiB

// Kernel B smem
constexpr int B_OFF_TS  = 0;                        // ts[64][32]
constexpr int B_OFF_W2D = 2048;                     // float4[64][25]
constexpr int W2D_ROW   = 25;
constexpr int B_OFF_WG  = B_OFF_W2D + 64 * W2D_ROW * 4;   // 8448
constexpr int B_OFF_XH  = B_OFF_WG + 49 * TP;             // 10016
constexpr int B_SMEM_FLOATS = B_OFF_XH + HALO_SZ;         // 12256 = 47.9 KiB
}
using namespace cfg;

__device__ float t_buf[4 * CR * HW * HW];   // 3.2 MB scratch (allowed: static)

// ===========================================================================
// Kernel A: t = relu(BN(x @ W1^T + b1))
// ===========================================================================
__global__ void __launch_bounds__(256) t_gemm_kernel(
    const float* __restrict__ x,
    const float* __restrict__ W1, const float* __restrict__ b1,
    const float* __restrict__ gamma, const float* __restrict__ beta,
    const float* __restrict__ mean, const float* __restrict__ var)
{
    extern __shared__ float smem[];
    ulonglong2* W1d = (ulonglong2*)smem;       // [cc][33]: (w_o0 dup | w_o1 dup)
    float* xs = smem + A_OFF_XS;               // [64ch][32px]

    const int tid = threadIdx.x;
    const int b   = blockIdx.z;
    const int h0  = blockIdx.y * TH;
    const int w0  = blockIdx.x * TW;
    const int op  = tid >> 3;                  // out pair (2op, 2op+1)
    const int pxq = tid & 7;                   // pixel quad 4pxq..4pxq+3
    U64 a00 = 0, a01 = 0, a10 = 0, a11 = 0;

    for (int chunk = 0; chunk < 4; chunk++) {
        const int c0 = chunk * 64;
        {
            int idx = tid;
            #pragma unroll
            for (int r = 0; r < 2; r++) {
                const int cc = idx >> 3, py = (idx >> 1) & 3, hf = idx & 1;
                const float4 v = *(const float4*)&x[((b * C + c0 + cc) * HW + h0 + py) * HW + w0 + hf * 4];
                *(float4*)&xs[cc * TP + py * TW + hf * 4] = v;
                idx += 256;
            }
        }
        #pragma unroll
        for (int r = 0; r < 8; r++) {
            const int idx = tid + 256 * r;
            const int cc = idx & 63, o2 = idx >> 6;
            const float v0 = __ldg(&W1[(2 * o2) * C + c0 + cc]);
            const float v1 = __ldg(&W1[(2 * o2 + 1) * C + c0 + cc]);
            *(float4*)&W1d[cc * W1D_ROW + o2] = make_float4(v0, v0, v1, v1);
        }
        __syncthreads();

        #pragma unroll 8
        for (int cc = 0; cc < 64; cc++) {
            const ulonglong2 tv = *(const ulonglong2*)&xs[cc * TP + pxq * 4];
            const ulonglong2 wv = W1d[cc * W1D_ROW + op];
            a00 = ffma2(wv.x, tv.x, a00);
            a01 = ffma2(wv.x, tv.y, a01);
            a10 = ffma2(wv.y, tv.x, a10);
            a11 = ffma2(wv.y, tv.y, a11);
        }
        __syncthreads();
    }

    // BN fold + relu + store to t_buf
    const int py = pxq >> 1, pw = (pxq & 1) * 4;
    #pragma unroll
    for (int u = 0; u < 2; u++) {
        const int o = 2 * op + u;
        const float a  = __ldg(&gamma[o]) * rsqrtf(__ldg(&var[o]) + EPSV);
        const float bb = __ldg(&b1[o]) * a + __ldg(&beta[o]) - __ldg(&mean[o]) * a;
        const float2 p0 = unpack2(u ? a10 : a00);
        const float2 p1 = unpack2(u ? a11 : a01);
        float4 r;
        r.x = fmaxf(p0.x * a + bb, 0.f);
        r.y = fmaxf(p0.y * a + bb, 0.f);
        r.z = fmaxf(p1.x * a + bb, 0.f);
        r.w = fmaxf(p1.y * a + bb, 0.f);
        *(float4*)&t_buf[((b * CR + o) * HW + h0 + py) * HW + w0 + pw] = r;
    }
}

// ===========================================================================
// Kernel B: kernel-GEMM + involution, 4 groups per block (split x4)
// ===========================================================================
__global__ void __launch_bounds__(256) involution_kernel(
    const float* __restrict__ x,
    const float* __restrict__ W2, const float* __restrict__ b2,
    float* __restrict__ out)
{
    extern __shared__ float smem[];
    float* ts = smem + B_OFF_TS;
    ulonglong2* W2d = (ulonglong2*)(smem + B_OFF_W2D);   // [cc][25]
    float* wg = smem + B_OFF_WG;
    float* xh = smem + B_OFF_XH;

    const int tid = threadIdx.x;
    const int z   = blockIdx.z;        // 0..15
    const int b   = z >> 2;
    const int gs  = z & 3;             // group split
    const int h0  = blockIdx.y * TH;
    const int w0  = blockIdx.x * TW;

    // ts tile load (cp.async 16B x2 per thread)
    {
        int idx = tid;
        #pragma unroll
        for (int r = 0; r < 2; r++) {
            const int cc = idx >> 3, py = (idx >> 1) & 3, hf = idx & 1;
            cp_async16(&ts[cc * TP + py * TW + hf * 4],
                       &t_buf[((b * CR + cc) * HW + h0 + py) * HW + w0 + hf * 4]);
            idx += 256;
        }
        cp_commit();
    }

    // phase-2 ids
    const int kp   = tid >> 3;         // k-pair (2kp, 2kp+1), active kp<25
    const int pxq2 = tid & 7;
    // phase-3 ids (threads 0..127): (2 channels, 2 pixels)
    const int cs   = tid >> 4;         // 0..7 for tid<128 -> channels 2cs, 2cs+1
    const int pxp  = tid & 15;         // pixel pair 2pxp, 2pxp+1
    const int py3  = pxp >> 2;
    const int col3 = (pxp & 3) * 2;

    for (int gi = 0; gi < G / SPLIT; gi++) {
        const int g = gs * (G / SPLIT) + gi;

        // halo via cp.async 4B with zero-fill for padding
        for (int idx = tid; idx < HALO_SZ; idx += 256) {
            const int c   = idx / HALO_CH;
            const int rem = idx - c * HALO_CH;
            const int r   = rem / HALO_W;
            const int cl  = rem - r * HALO_W;
            const int gh  = h0 + r - PAD, gw = w0 + cl - PAD;
            const bool inb = ((unsigned)gh < (unsigned)HW) & ((unsigned)gw < (unsigned)HW);
            const float* src = &x[((b * C + g * Cg + c) * HW + (inb ? gh : 0)) * HW + (inb ? gw : 0)];
            cp_async4z(&xh[idx], src, inb ? 4 : 0);
        }
        cp_commit();

        // W2 group -> W2d[cc][kq] = (w_k0 x2, w_k1 x2)
        {
            int idx = tid;
            #pragma unroll
            for (int r = 0; r < 7; r++) {
                if (idx < 1600) {
                    const int cc = idx & 63, kq = idx >> 6;
                    const int k0 = 2 * kq, k1 = 2 * kq + 1;
                    const float v0 = __ldg(&W2[(g * 49 + k0) * CR + cc]);
                    const float v1 = (k1 < 49) ? __ldg(&W2[(g * 49 + k1) * CR + cc]) : 0.f;
                    *(float4*)&W2d[cc * W2D_ROW + kq] = make_float4(v0, v0, v1, v1);
                }
                idx += 256;
            }
        }
        cp_wait1();              // ts done (1st iter); halo still in flight
        __syncthreads();

        // phase 2: wg[k][p] = sum_cc W2g[k][cc] * t[cc][p] + b2[k]
        if (kp < 25) {
            const int k0 = 2 * kp, k1 = 2 * kp + 1;
            const float z0 = __ldg(&b2[g * 49 + k0]);
            const float z1 = (k1 < 49) ? __ldg(&b2[g * 49 + k1]) : 0.f;
            U64 b00 = pack2(z0, z0), b01 = b00;
            U64 b10 = pack2(z1, z1), b11 = b10;
            #pragma unroll 8
            for (int cc = 0; cc < 64; cc++) {
                const ulonglong2 tv = *(const ulonglong2*)&ts[cc * TP + pxq2 * 4];
                const ulonglong2 wv = W2d[cc * W2D_ROW + kp];
                b00 = ffma2(wv.x, tv.x, b00);
                b01 = ffma2(wv.x, tv.y, b01);
                b10 = ffma2(wv.y, tv.x, b10);
                b11 = ffma2(wv.y, tv.y, b11);
            }
            *(U64*)&wg[k0 * TP + pxq2 * 4]     = b00;
            *(U64*)&wg[k0 * TP + pxq2 * 4 + 2] = b01;
            if (k1 < 49) {
                *(U64*)&wg[k1 * TP + pxq2 * 4]     = b10;
                *(U64*)&wg[k1 * TP + pxq2 * 4 + 2] = b11;
            }
        }
        cp_wait0();              // halo landed (overlapped with phase 2)
        __syncthreads();

        // phase 3: involution — thread owns (channels 2cs,2cs+1; pixels 2pxp,2pxp+1)
        if (tid < 128) {
            const int c0 = 2 * cs;
            const float* xa = &xh[c0 * HALO_CH + py3 * HALO_W + col3];
            const float* xb = xa + HALO_CH;
            float o00 = 0.f, o01 = 0.f, o10 = 0.f, o11 = 0.f;
            #pragma unroll
            for (int i = 0; i < KS; i++) {
                const float* r0 = xa + i * HALO_W;
                const float* r1 = xb + i * HALO_W;
                float x0[9], x1[9];
                {
                    const float2 a0 = *(const float2*)(r0 + 0);
                    const float2 a1 = *(const float2*)(r0 + 2);
                    const float2 a2 = *(const float2*)(r0 + 4);
                    const float2 a3 = *(const float2*)(r0 + 6);
                    x0[0]=a0.x; x0[1]=a0.y; x0[2]=a1.x; x0[3]=a1.y;
                    x0[4]=a2.x; x0[5]=a2.y; x0[6]=a3.x; x0[7]=a3.y; x0[8]=r0[8];
                    const float2 c0v = *(const float2*)(r1 + 0);
                    const float2 c1v = *(const float2*)(r1 + 2);
                    const float2 c2v = *(const float2*)(r1 + 4);
                    const float2 c3v = *(const float2*)(r1 + 6);
                    x1[0]=c0v.x; x1[1]=c0v.y; x1[2]=c1v.x; x1[3]=c1v.y;
                    x1[4]=c2v.x; x1[5]=c2v.y; x1[6]=c3v.x; x1[7]=c3v.y; x1[8]=r1[8];
                }
                #pragma unroll
                for (int j = 0; j < KS; j++) {
                    const float2 wv = *(const float2*)&wg[(i * KS + j) * TP + 2 * pxp];
                    o00 = fmaf(x0[j],     wv.x, o00);
                    o01 = fmaf(x0[j + 1], wv.y, o01);
                    o10 = fmaf(x1[j],     wv.x, o10);
                    o11 = fmaf(x1[j + 1], wv.y, o11);
                }
            }
            const int base = ((b * C + g * Cg + c0) * HW + h0 + py3) * HW + w0 + col3;
            *(float2*)&out[base]           = make_float2(o00, o01);
            *(float2*)&out[base + HW * HW] = make_float2(o10, o11);
        }
        __syncthreads();
    }
}

extern "C" void kernel_launch(void* const* d_in, const int* in_sizes, int n_in,
                              void* d_out, int out_size) {
    const float* x     = (const float*)d_in[0];
    const float* W1    = (const float*)d_in[1];
    const float* b1    = (const float*)d_in[2];
    const float* gamma = (const float*)d_in[3];
    const float* beta  = (const float*)d_in[4];
    const float* mean  = (const float*)d_in[5];
    const float* var   = (const float*)d_in[6];
    const float* W2    = (const float*)d_in[7];
    const float* b2    = (const float*)d_in[8];
    float* out = (float*)d_out;

    const size_t smemA = (size_t)A_SMEM_FLOATS * sizeof(float);
    const size_t smemB = (size_t)B_SMEM_FLOATS * sizeof(float);
    cudaFuncSetAttribute(t_gemm_kernel,
                         cudaFuncAttributeMaxDynamicSharedMemorySize, (int)smemA);
    cudaFuncSetAttribute(involution_kernel,
                         cudaFuncAttributeMaxDynamicSharedMemorySize, (int)smemB);

    dim3 gridA(HW / TW, HW / TH, 4);            // 392 blocks
    t_gemm_kernel<<<gridA, 256, smemA>>>(x, W1, b1, gamma, beta, mean, var);

    dim3 gridB(HW / TW, HW / TH, 4 * SPLIT);    // 1568 blocks
    involution_kernel<<<gridB, 256, smemB>>>(x, W2, b2, out);
}